// round 10
// baseline (speedup 1.0000x reference)
#include <cuda_runtime.h>
#include <math.h>

// Repacked class boxes. Row = 64 floats (256B, line-aligned).
// Line 0 (f[0..31]):  f[2m]=lo_m, f[2m+1]=hi_m for dims m=0..13; f[28]=s; f[29]=b; f[30..31] pad
// Line 1 (f[32..55]): f[32+2m]=lo_{14+m}, f[33+2m]=hi_{14+m} for m=0..10 (dims 14..24); pad
// loss = b - inter_area * s reproduces the reference's 3-way where().
// Hot path: intersection is exactly 0 after dims 0..13 for ~all pairs (widths ~1,
// centers +-10000), so only line 0 of each row is read; line 1 via rare branch.
#define MAX_CLASSES 100000
__device__ float g_rows[(size_t)MAX_CLASSES * 64];
__device__ double g_acc;
__device__ unsigned int g_done;

#define RPB 64   // rows per repack block

__global__ __launch_bounds__(256)
void repack_kernel(const float* __restrict__ emb, int n_classes)
{
    __shared__ float sm[RPB * 50];
    if (blockIdx.x == 0 && threadIdx.x == 0) { g_acc = 0.0; g_done = 0u; }

    int r0 = blockIdx.x * RPB;
    int nrows = n_classes - r0;
    if (nrows > RPB) nrows = RPB;
    int nflt = nrows * 50;

    // r0 multiple of 64 -> byte offset r0*200 is 128B-aligned; stage coalesced.
    const float4* s4 = (const float4*)(emb + (size_t)r0 * 50);
    float4* d4 = (float4*)sm;
    int n4 = nflt >> 2;
    for (int i = threadIdx.x; i < n4; i += 256) d4[i] = s4[i];
    for (int i = (n4 << 2) + threadIdx.x; i < nflt; i += 256)
        sm[i] = ((const float*)s4)[i];
    __syncthreads();

    int g = threadIdx.x & 7;
#pragma unroll
    for (int half = 0; half < 2; half++) {
        int lr = (threadIdx.x >> 3) + half * 32;
        bool live = (lr < nrows);
        int lre = live ? lr : 0;
        const float* r = sm + lre * 50;   // c[k]=r[k], o[k]=|r[25+k]|

        float part = 1.0f;

        // line 0 piece: lanes 0..6 hold dims 2g, 2g+1
        float4 out1 = make_float4(0.f, 0.f, 0.f, 0.f);
        if (g < 7) {
            float c0 = r[2 * g],     o0 = fabsf(r[25 + 2 * g]);
            float c1 = r[2 * g + 1], o1 = fabsf(r[26 + 2 * g]);
            out1 = make_float4(c0 - o0, c0 + o0, c1 - o1, c1 + o1);
            part *= (2.0f * o0) * (2.0f * o1);
        }

        // line 1 piece: lanes 0..4 hold dims 14+2g, 15+2g; lane 5 holds dim 24
        float4 out2 = make_float4(0.f, 0.f, 0.f, 0.f);
        if (g <= 4) {
            int k = 14 + 2 * g;
            float c0 = r[k],     o0 = fabsf(r[25 + k]);
            float c1 = r[k + 1], o1 = fabsf(r[26 + k]);
            out2 = make_float4(c0 - o0, c0 + o0, c1 - o1, c1 + o1);
            part *= (2.0f * o0) * (2.0f * o1);
        } else if (g == 5) {
            float c24 = r[24], o24 = fabsf(r[49]);
            out2.x = c24 - o24;
            out2.y = c24 + o24;
            part *= 2.0f * o24;
        }

        // area = product across the 8-lane group (dims 0..24 covered once each)
        part *= __shfl_xor_sync(0xFFFFFFFFu, part, 1);
        part *= __shfl_xor_sync(0xFFFFFFFFu, part, 2);
        part *= __shfl_xor_sync(0xFFFFFFFFu, part, 4);

        if (g == 7) {
            float s, b;
            if (part == 0.0f)      { s = 0.0f;            b = 0.0f; }
            else if (isinf(part))  { s = 1.0f / 20000.0f; b = 1.0f; }
            else                   { s = 1.0f / part;     b = 1.0f; }
            out1.x = s;
            out1.y = b;
        }

        if (live) {
            float4* out = (float4*)(g_rows + (size_t)(r0 + lr) * 64);
            out[g] = out1;                    // line 0: dims 0..13 + (s,b)
            if (g <= 5) out[8 + g] = out2;    // line 1: dims 14..24
        }
    }
}

// 8 lanes per pair, grid-stride, uniform trip count. Hot path reads one 128B
// line per row; dims 14..24 only via warp-uniform rare branch.
__global__ __launch_bounds__(256)
void pairs_kernel(const int2* __restrict__ nf1, int n_pairs, int n_groups,
                  int n_iter, float* __restrict__ out)
{
    int tid   = blockIdx.x * blockDim.x + threadIdx.x;
    int group = tid >> 3;
    int g     = tid & 7;

    float acc = 0.0f;

    for (int it = 0; it < n_iter; it++) {
        int pair = group + it * n_groups;
        bool live = (pair < n_pairs);
        int pe = live ? pair : (n_pairs - 1);

        int2 p = __ldg(nf1 + pe);
        const float4* A = (const float4*)(g_rows + (size_t)p.x * 64);
        const float4* B = (const float4*)(g_rows + (size_t)p.y * 64);

        float4 a1 = __ldg(A + g);
        float4 b1 = __ldg(B + g);

        float prod;
        float s = 0.0f, b = 0.0f;
        if (g < 7) {
            float w0 = fminf(a1.y, b1.y) - fmaxf(a1.x, b1.x);
            float w1 = fminf(a1.w, b1.w) - fmaxf(a1.z, b1.z);
            prod = fmaxf(w0, 0.0f) * fmaxf(w1, 0.0f);
        } else {
            prod = 1.0f;
            s = a1.x;   // C-row 1/area (or 1/20000, or 0)
            b = a1.y;   // 1 (or 0)
        }

        prod *= __shfl_xor_sync(0xFFFFFFFFu, prod, 1);
        prod *= __shfl_xor_sync(0xFFFFFFFFu, prod, 2);
        prod *= __shfl_xor_sync(0xFFFFFFFFu, prod, 4);

        // Rare: some group in this warp still has nonzero intersection after
        // dims 0..13 -> fold in dims 14..24 from line 1. prod is group-uniform.
        if (__any_sync(0xFFFFFFFFu, prod > 0.0f)) {
            float extra = 1.0f;
            if (prod > 0.0f && g <= 5) {
                float4 a2 = __ldg(A + 8 + g);
                float4 b2 = __ldg(B + 8 + g);
                float u0 = fminf(a2.y, b2.y) - fmaxf(a2.x, b2.x);
                extra = fmaxf(u0, 0.0f);
                if (g <= 4) {
                    float u1 = fminf(a2.w, b2.w) - fmaxf(a2.z, b2.z);
                    extra *= fmaxf(u1, 0.0f);
                }
            }
            extra *= __shfl_xor_sync(0xFFFFFFFFu, extra, 1);
            extra *= __shfl_xor_sync(0xFFFFFFFFu, extra, 2);
            extra *= __shfl_xor_sync(0xFFFFFFFFu, extra, 4);
            prod *= extra;
        }

        if (g == 7 && live) {
            float loss = b - prod * s;
            float rl = fmaxf(loss, 0.0f);
            acc += rl * rl;
        }
    }

    // warp reduce
#pragma unroll
    for (int off = 16; off > 0; off >>= 1)
        acc += __shfl_down_sync(0xFFFFFFFFu, acc, off);

    __shared__ float smred[8];
    int lane = threadIdx.x & 31;
    int wid  = threadIdx.x >> 5;
    if (lane == 0) smred[wid] = acc;
    __syncthreads();
    if (wid == 0) {
        float v = (lane < 8) ? smred[lane] : 0.0f;
#pragma unroll
        for (int off = 4; off > 0; off >>= 1)
            v += __shfl_down_sync(0xFFFFFFFFu, v, off);
        if (lane == 0) {
            atomicAdd(&g_acc, (double)v);
            __threadfence();
            unsigned int old = atomicAdd(&g_done, 1u);
            if (old == gridDim.x - 1) {
                double total = *((volatile double*)&g_acc);
                out[0] = (float)sqrt(total);
            }
        }
    }
}

extern "C" void kernel_launch(void* const* d_in, const int* in_sizes, int n_in,
                              void* d_out, int out_size)
{
    const float* class_embeds = (const float*)d_in[0];
    const int2*  nf1          = (const int2*)d_in[1];
    int n_classes = in_sizes[0] / 50;
    int n_pairs   = in_sizes[1] / 2;

    repack_kernel<<<(n_classes + RPB - 1) / RPB, 256>>>(class_embeds, n_classes);

    {
        const int grid = 2368;              // 2 short waves; backfill hides spread
        const int n_groups = grid * 256 / 8;
        int n_iter = (n_pairs + n_groups - 1) / n_groups;
        pairs_kernel<<<grid, 256>>>(nf1, n_pairs, n_groups, n_iter, (float*)d_out);
    }
}

// round 11
// speedup vs baseline: 1.4620x; 1.4620x over previous
#include <cuda_runtime.h>
#include <math.h>

// Repacked class boxes. Row = 64 floats (256B, line-aligned).
// Line 0 (f[0..31]):  f[2m]=lo_m, f[2m+1]=hi_m for dims m=0..13; f[28]=s; f[29]=b; f[30..31] pad
// Line 1 (f[32..55]): f[32+2m]=lo_{14+m}, f[33+2m]=hi_{14+m} for m=0..10 (dims 14..24); pad
// loss = b - inter_area * s reproduces the reference's 3-way where().
// Hot path: intersection is exactly 0 after dims 0..13 for ~all pairs (widths ~1,
// centers +-10000), so only line 0 of each row is read; line 1 via rare branch.
#define MAX_CLASSES 100000
__device__ float g_rows[(size_t)MAX_CLASSES * 64];
__device__ double g_acc;
__device__ unsigned int g_done;

#define RPB 64   // rows per repack block

__global__ __launch_bounds__(256)
void repack_kernel(const float* __restrict__ emb, int n_classes)
{
    __shared__ float sm[RPB * 50];
    if (blockIdx.x == 0 && threadIdx.x == 0) { g_acc = 0.0; g_done = 0u; }

    int r0 = blockIdx.x * RPB;
    int nrows = n_classes - r0;
    if (nrows > RPB) nrows = RPB;
    int nflt = nrows * 50;

    // r0 multiple of 64 -> byte offset r0*200 is 128B-aligned; stage coalesced.
    const float4* s4 = (const float4*)(emb + (size_t)r0 * 50);
    float4* d4 = (float4*)sm;
    int n4 = nflt >> 2;
    for (int i = threadIdx.x; i < n4; i += 256) d4[i] = s4[i];
    for (int i = (n4 << 2) + threadIdx.x; i < nflt; i += 256)
        sm[i] = ((const float*)s4)[i];
    __syncthreads();

    int g = threadIdx.x & 7;
#pragma unroll
    for (int half = 0; half < 2; half++) {
        int lr = (threadIdx.x >> 3) + half * 32;
        bool live = (lr < nrows);
        int lre = live ? lr : 0;
        const float* r = sm + lre * 50;   // c[k]=r[k], o[k]=|r[25+k]|

        float part = 1.0f;

        // line 0 piece: lanes 0..6 hold dims 2g, 2g+1
        float4 out1 = make_float4(0.f, 0.f, 0.f, 0.f);
        if (g < 7) {
            float c0 = r[2 * g],     o0 = fabsf(r[25 + 2 * g]);
            float c1 = r[2 * g + 1], o1 = fabsf(r[26 + 2 * g]);
            out1 = make_float4(c0 - o0, c0 + o0, c1 - o1, c1 + o1);
            part *= (2.0f * o0) * (2.0f * o1);
        }

        // line 1 piece: lanes 0..4 hold dims 14+2g, 15+2g; lane 5 holds dim 24
        float4 out2 = make_float4(0.f, 0.f, 0.f, 0.f);
        if (g <= 4) {
            int k = 14 + 2 * g;
            float c0 = r[k],     o0 = fabsf(r[25 + k]);
            float c1 = r[k + 1], o1 = fabsf(r[26 + k]);
            out2 = make_float4(c0 - o0, c0 + o0, c1 - o1, c1 + o1);
            part *= (2.0f * o0) * (2.0f * o1);
        } else if (g == 5) {
            float c24 = r[24], o24 = fabsf(r[49]);
            out2.x = c24 - o24;
            out2.y = c24 + o24;
            part *= 2.0f * o24;
        }

        // area = product across the 8-lane group (dims 0..24 covered once each)
        part *= __shfl_xor_sync(0xFFFFFFFFu, part, 1);
        part *= __shfl_xor_sync(0xFFFFFFFFu, part, 2);
        part *= __shfl_xor_sync(0xFFFFFFFFu, part, 4);

        if (g == 7) {
            float s, b;
            if (part == 0.0f)      { s = 0.0f;            b = 0.0f; }
            else if (isinf(part))  { s = 1.0f / 20000.0f; b = 1.0f; }
            else                   { s = 1.0f / part;     b = 1.0f; }
            out1.x = s;
            out1.y = b;
        }

        if (live) {
            float4* out = (float4*)(g_rows + (size_t)(r0 + lr) * 64);
            out[g] = out1;                    // line 0: dims 0..13 + (s,b)
            if (g <= 5) out[8 + g] = out2;    // line 1: dims 14..24
        }
    }
}

// 8 lanes per pair, grid-stride, uniform trip count. Hot path reads one 128B
// line per row; dims 14..24 only via warp-uniform rare branch.
__global__ __launch_bounds__(256)
void pairs_kernel(const int2* __restrict__ nf1, int n_pairs, int n_groups,
                  int n_iter, float* __restrict__ out)
{
    int tid   = blockIdx.x * blockDim.x + threadIdx.x;
    int group = tid >> 3;
    int g     = tid & 7;

    float acc = 0.0f;

    for (int it = 0; it < n_iter; it++) {
        int pair = group + it * n_groups;
        bool live = (pair < n_pairs);
        int pe = live ? pair : (n_pairs - 1);

        int2 p = __ldg(nf1 + pe);
        const float4* A = (const float4*)(g_rows + (size_t)p.x * 64);
        const float4* B = (const float4*)(g_rows + (size_t)p.y * 64);

        float4 a1 = __ldg(A + g);
        float4 b1 = __ldg(B + g);

        float prod;
        float s = 0.0f, b = 0.0f;
        if (g < 7) {
            float w0 = fminf(a1.y, b1.y) - fmaxf(a1.x, b1.x);
            float w1 = fminf(a1.w, b1.w) - fmaxf(a1.z, b1.z);
            prod = fmaxf(w0, 0.0f) * fmaxf(w1, 0.0f);
        } else {
            prod = 1.0f;
            s = a1.x;   // C-row 1/area (or 1/20000, or 0)
            b = a1.y;   // 1 (or 0)
        }

        prod *= __shfl_xor_sync(0xFFFFFFFFu, prod, 1);
        prod *= __shfl_xor_sync(0xFFFFFFFFu, prod, 2);
        prod *= __shfl_xor_sync(0xFFFFFFFFu, prod, 4);

        // Rare: some group in this warp still has nonzero intersection after
        // dims 0..13 -> fold in dims 14..24 from line 1. prod is group-uniform.
        if (__any_sync(0xFFFFFFFFu, prod > 0.0f)) {
            float extra = 1.0f;
            if (prod > 0.0f && g <= 5) {
                float4 a2 = __ldg(A + 8 + g);
                float4 b2 = __ldg(B + 8 + g);
                float u0 = fminf(a2.y, b2.y) - fmaxf(a2.x, b2.x);
                extra = fmaxf(u0, 0.0f);
                if (g <= 4) {
                    float u1 = fminf(a2.w, b2.w) - fmaxf(a2.z, b2.z);
                    extra *= fmaxf(u1, 0.0f);
                }
            }
            extra *= __shfl_xor_sync(0xFFFFFFFFu, extra, 1);
            extra *= __shfl_xor_sync(0xFFFFFFFFu, extra, 2);
            extra *= __shfl_xor_sync(0xFFFFFFFFu, extra, 4);
            prod *= extra;
        }

        if (g == 7 && live) {
            float loss = b - prod * s;
            float rl = fmaxf(loss, 0.0f);
            acc += rl * rl;
        }
    }

    // warp reduce
#pragma unroll
    for (int off = 16; off > 0; off >>= 1)
        acc += __shfl_down_sync(0xFFFFFFFFu, acc, off);

    __shared__ float smred[8];
    int lane = threadIdx.x & 31;
    int wid  = threadIdx.x >> 5;
    if (lane == 0) smred[wid] = acc;
    __syncthreads();
    if (wid == 0) {
        float v = (lane < 8) ? smred[lane] : 0.0f;
#pragma unroll
        for (int off = 4; off > 0; off >>= 1)
            v += __shfl_down_sync(0xFFFFFFFFu, v, off);
        if (lane == 0) {
            atomicAdd(&g_acc, (double)v);
            __threadfence();
            unsigned int old = atomicAdd(&g_done, 1u);
            if (old == gridDim.x - 1) {
                double total = *((volatile double*)&g_acc);
                out[0] = (float)sqrt(total);
            }
        }
    }
}

extern "C" void kernel_launch(void* const* d_in, const int* in_sizes, int n_in,
                              void* d_out, int out_size)
{
    const float* class_embeds = (const float*)d_in[0];
    const int2*  nf1          = (const int2*)d_in[1];
    int n_classes = in_sizes[0] / 50;
    int n_pairs   = in_sizes[1] / 2;

    repack_kernel<<<(n_classes + RPB - 1) / RPB, 256>>>(class_embeds, n_classes);

    {
        const int grid = 2368;              // 2 short waves; backfill hides spread
        const int n_groups = grid * 256 / 8;
        int n_iter = (n_pairs + n_groups - 1) / n_groups;
        pairs_kernel<<<grid, 256>>>(nf1, n_pairs, n_groups, n_iter, (float*)d_out);
    }
}

// round 12
// speedup vs baseline: 1.5181x; 1.0384x over previous
#include <cuda_runtime.h>
#include <math.h>

// Repacked class boxes. Row = 64 floats (256B, line-aligned).
// Line 0 (f[0..31]):  f[2m]=lo_m, f[2m+1]=hi_m for dims m=0..13; f[28]=s; f[29]=b; pad
// Line 1 (f[32..55]): lo/hi of dims 14..24; pad
// loss = b - inter_area * s reproduces the reference's 3-way where().
// Hot path: some dim in 0..13 has zero overlap for ~all pairs -> inter=0 ->
// rl^2 = b (b in {0,1}); detected with ONE ballot, no shfl reduce, no line 1.
#define MAX_CLASSES 100000
__device__ float g_rows[(size_t)MAX_CLASSES * 64];
__device__ double g_acc;
__device__ unsigned int g_done;

#define RPB 64   // rows per repack block

__global__ __launch_bounds__(256)
void repack_kernel(const float* __restrict__ emb, int n_classes)
{
    __shared__ float sm[RPB * 50];
    if (blockIdx.x == 0 && threadIdx.x == 0) { g_acc = 0.0; g_done = 0u; }

    int r0 = blockIdx.x * RPB;
    int nrows = n_classes - r0;
    if (nrows > RPB) nrows = RPB;
    int nflt = nrows * 50;

    const float4* s4 = (const float4*)(emb + (size_t)r0 * 50);
    float4* d4 = (float4*)sm;
    int n4 = nflt >> 2;
    for (int i = threadIdx.x; i < n4; i += 256) d4[i] = s4[i];
    for (int i = (n4 << 2) + threadIdx.x; i < nflt; i += 256)
        sm[i] = ((const float*)s4)[i];
    __syncthreads();

    int g = threadIdx.x & 7;
#pragma unroll
    for (int half = 0; half < 2; half++) {
        int lr = (threadIdx.x >> 3) + half * 32;
        bool live = (lr < nrows);
        int lre = live ? lr : 0;
        const float* r = sm + lre * 50;   // c[k]=r[k], o[k]=|r[25+k]|

        float part = 1.0f;

        float4 out1 = make_float4(0.f, 0.f, 0.f, 0.f);
        if (g < 7) {
            float c0 = r[2 * g],     o0 = fabsf(r[25 + 2 * g]);
            float c1 = r[2 * g + 1], o1 = fabsf(r[26 + 2 * g]);
            out1 = make_float4(c0 - o0, c0 + o0, c1 - o1, c1 + o1);
            part *= (2.0f * o0) * (2.0f * o1);
        }

        float4 out2 = make_float4(0.f, 0.f, 0.f, 0.f);
        if (g <= 4) {
            int k = 14 + 2 * g;
            float c0 = r[k],     o0 = fabsf(r[25 + k]);
            float c1 = r[k + 1], o1 = fabsf(r[26 + k]);
            out2 = make_float4(c0 - o0, c0 + o0, c1 - o1, c1 + o1);
            part *= (2.0f * o0) * (2.0f * o1);
        } else if (g == 5) {
            float c24 = r[24], o24 = fabsf(r[49]);
            out2.x = c24 - o24;
            out2.y = c24 + o24;
            part *= 2.0f * o24;
        }

        part *= __shfl_xor_sync(0xFFFFFFFFu, part, 1);
        part *= __shfl_xor_sync(0xFFFFFFFFu, part, 2);
        part *= __shfl_xor_sync(0xFFFFFFFFu, part, 4);

        if (g == 7) {
            float s, b;
            if (part == 0.0f)      { s = 0.0f;            b = 0.0f; }
            else if (isinf(part))  { s = 1.0f / 20000.0f; b = 1.0f; }
            else                   { s = 1.0f / part;     b = 1.0f; }
            out1.x = s;
            out1.y = b;
        }

        if (live) {
            float4* out = (float4*)(g_rows + (size_t)(r0 + lr) * 64);
            out[g] = out1;                    // line 0: dims 0..13 + (s,b)
            if (g <= 5) out[8 + g] = out2;    // line 1: dims 14..24
        }
    }
}

// Full (rare) evaluation for one pair: shfl product over lane partials,
// plus line-1 dims when still positive. Returns group-uniform prod.
__device__ __forceinline__ float rare_full_prod(
    const float4* A, const float4* B, int g, float part)
{
    float prod = part;
    prod *= __shfl_xor_sync(0xFFFFFFFFu, prod, 1);
    prod *= __shfl_xor_sync(0xFFFFFFFFu, prod, 2);
    prod *= __shfl_xor_sync(0xFFFFFFFFu, prod, 4);

    if (__any_sync(0xFFFFFFFFu, prod > 0.0f)) {
        float extra = 1.0f;
        if (prod > 0.0f && g <= 5) {
            float4 a2 = __ldg(A + 8 + g);
            float4 b2 = __ldg(B + 8 + g);
            float u0 = fminf(a2.y, b2.y) - fmaxf(a2.x, b2.x);
            extra = fmaxf(u0, 0.0f);
            if (g <= 4) {
                float u1 = fminf(a2.w, b2.w) - fmaxf(a2.z, b2.z);
                extra *= fmaxf(u1, 0.0f);
            }
        }
        extra *= __shfl_xor_sync(0xFFFFFFFFu, extra, 1);
        extra *= __shfl_xor_sync(0xFFFFFFFFu, extra, 2);
        extra *= __shfl_xor_sync(0xFFFFFFFFu, extra, 4);
        prod *= extra;
    }
    return prod;
}

// 8 lanes per pair, grid-stride. Unguarded main loop + one guarded tail.
__global__ __launch_bounds__(256)
void pairs_kernel(const int2* __restrict__ nf1, int n_pairs, int n_groups,
                  int n_full, int rem, float* __restrict__ out)
{
    int tid   = blockIdx.x * blockDim.x + threadIdx.x;
    int group = tid >> 3;
    int g     = tid & 7;
    int gsh   = threadIdx.x & 24;   // (group within warp) * 8

    float acc = 0.0f;
    int pair = group;

    for (int it = 0; it < n_full; it++, pair += n_groups) {
        int2 p = __ldg(nf1 + pair);
        const float4* A = (const float4*)(g_rows + (size_t)p.x * 64);
        const float4* B = (const float4*)(g_rows + (size_t)p.y * 64);

        float4 a1 = __ldg(A + g);
        float4 b1 = __ldg(B + g);

        float part, s = 0.0f, b = 0.0f;
        if (g < 7) {
            float w0 = fminf(a1.y, b1.y) - fmaxf(a1.x, b1.x);
            float w1 = fminf(a1.w, b1.w) - fmaxf(a1.z, b1.z);
            part = fmaxf(w0, 0.0f) * fmaxf(w1, 0.0f);
        } else {
            part = 1.0f;
            s = a1.x;
            b = a1.y;
        }

        unsigned ball = __ballot_sync(0xFFFFFFFFu, part > 0.0f);
        bool galive = (((ball >> gsh) & 0x7Fu) == 0x7Fu);

        if (__any_sync(0xFFFFFFFFu, galive)) {
            // rare: at least one group in warp has nonzero overlap on dims 0..13
            float prod = rare_full_prod(A, B, g, part);
            if (g == 7) {
                float loss = b - prod * s;
                float rl = fmaxf(loss, 0.0f);
                acc += rl * rl;
            }
        } else {
            // hot: inter_area == 0 -> rl^2 = b (b in {0,1})
            if (g == 7) acc += b;
        }
    }

    if (rem) {   // one guarded tail iteration (rem is uniform)
        bool live = (pair < n_pairs);
        int pe = live ? pair : (n_pairs - 1);
        int2 p = __ldg(nf1 + pe);
        const float4* A = (const float4*)(g_rows + (size_t)p.x * 64);
        const float4* B = (const float4*)(g_rows + (size_t)p.y * 64);

        float4 a1 = __ldg(A + g);
        float4 b1 = __ldg(B + g);

        float part, s = 0.0f, b = 0.0f;
        if (g < 7) {
            float w0 = fminf(a1.y, b1.y) - fmaxf(a1.x, b1.x);
            float w1 = fminf(a1.w, b1.w) - fmaxf(a1.z, b1.z);
            part = fmaxf(w0, 0.0f) * fmaxf(w1, 0.0f);
        } else {
            part = 1.0f;
            s = a1.x;
            b = a1.y;
        }

        unsigned ball = __ballot_sync(0xFFFFFFFFu, part > 0.0f);
        bool galive = (((ball >> gsh) & 0x7Fu) == 0x7Fu);

        if (__any_sync(0xFFFFFFFFu, galive)) {
            float prod = rare_full_prod(A, B, g, part);
            if (g == 7 && live) {
                float loss = b - prod * s;
                float rl = fmaxf(loss, 0.0f);
                acc += rl * rl;
            }
        } else {
            if (g == 7 && live) acc += b;
        }
    }

    // warp reduce
#pragma unroll
    for (int off = 16; off > 0; off >>= 1)
        acc += __shfl_down_sync(0xFFFFFFFFu, acc, off);

    __shared__ float smred[8];
    int lane = threadIdx.x & 31;
    int wid  = threadIdx.x >> 5;
    if (lane == 0) smred[wid] = acc;
    __syncthreads();
    if (wid == 0) {
        float v = (lane < 8) ? smred[lane] : 0.0f;
#pragma unroll
        for (int off = 4; off > 0; off >>= 1)
            v += __shfl_down_sync(0xFFFFFFFFu, v, off);
        if (lane == 0) {
            atomicAdd(&g_acc, (double)v);
            __threadfence();
            unsigned int old = atomicAdd(&g_done, 1u);
            if (old == gridDim.x - 1) {
                double total = *((volatile double*)&g_acc);
                out[0] = (float)sqrt(total);
            }
        }
    }
}

extern "C" void kernel_launch(void* const* d_in, const int* in_sizes, int n_in,
                              void* d_out, int out_size)
{
    const float* class_embeds = (const float*)d_in[0];
    const int2*  nf1          = (const int2*)d_in[1];
    int n_classes = in_sizes[0] / 50;
    int n_pairs   = in_sizes[1] / 2;

    repack_kernel<<<(n_classes + RPB - 1) / RPB, 256>>>(class_embeds, n_classes);

    {
        const int grid = 2368;              // 2 short waves; backfill hides spread
        const int n_groups = grid * 256 / 8;
        int n_full = n_pairs / n_groups;
        int rem    = n_pairs % n_groups;
        pairs_kernel<<<grid, 256>>>(nf1, n_pairs, n_groups, n_full, rem, (float*)d_out);
    }
}

// round 14
// speedup vs baseline: 1.5717x; 1.0353x over previous
#include <cuda_runtime.h>
#include <math.h>

// Repacked class boxes. Row = 64 floats (256B, line-aligned).
// Line 0 (f[0..31]):  f[2m]=lo_m, f[2m+1]=hi_m for dims m=0..13; f[28]=s; f[29]=b; pad
// Line 1 (f[32..55]): lo/hi of dims 14..24; pad
// loss = b - inter_area * s reproduces the reference's 3-way where().
// Hot path: some dim in 0..13 has zero overlap for ~all pairs -> inter=0 ->
// rl^2 = b (b in {0,1}); detected with ONE ballot, no shfl reduce, no line 1.
#define MAX_CLASSES 100000
__device__ float g_rows[(size_t)MAX_CLASSES * 64];
__device__ double g_acc;
__device__ unsigned int g_done;

#define RPB 64   // rows per repack block

__global__ __launch_bounds__(256)
void repack_kernel(const float* __restrict__ emb, int n_classes)
{
    __shared__ float sm[RPB * 50];
    if (blockIdx.x == 0 && threadIdx.x == 0) { g_acc = 0.0; g_done = 0u; }

    int r0 = blockIdx.x * RPB;
    int nrows = n_classes - r0;
    if (nrows > RPB) nrows = RPB;
    int nflt = nrows * 50;

    const float4* s4 = (const float4*)(emb + (size_t)r0 * 50);
    float4* d4 = (float4*)sm;
    int n4 = nflt >> 2;
    for (int i = threadIdx.x; i < n4; i += 256) d4[i] = s4[i];
    for (int i = (n4 << 2) + threadIdx.x; i < nflt; i += 256)
        sm[i] = ((const float*)s4)[i];
    __syncthreads();

    int g = threadIdx.x & 7;
#pragma unroll
    for (int half = 0; half < 2; half++) {
        int lr = (threadIdx.x >> 3) + half * 32;
        bool live = (lr < nrows);
        int lre = live ? lr : 0;
        const float* r = sm + lre * 50;   // c[k]=r[k], o[k]=|r[25+k]|

        float part = 1.0f;

        float4 out1 = make_float4(0.f, 0.f, 0.f, 0.f);
        if (g < 7) {
            float c0 = r[2 * g],     o0 = fabsf(r[25 + 2 * g]);
            float c1 = r[2 * g + 1], o1 = fabsf(r[26 + 2 * g]);
            out1 = make_float4(c0 - o0, c0 + o0, c1 - o1, c1 + o1);
            part *= (2.0f * o0) * (2.0f * o1);
        }

        float4 out2 = make_float4(0.f, 0.f, 0.f, 0.f);
        if (g <= 4) {
            int k = 14 + 2 * g;
            float c0 = r[k],     o0 = fabsf(r[25 + k]);
            float c1 = r[k + 1], o1 = fabsf(r[26 + k]);
            out2 = make_float4(c0 - o0, c0 + o0, c1 - o1, c1 + o1);
            part *= (2.0f * o0) * (2.0f * o1);
        } else if (g == 5) {
            float c24 = r[24], o24 = fabsf(r[49]);
            out2.x = c24 - o24;
            out2.y = c24 + o24;
            part *= 2.0f * o24;
        }

        part *= __shfl_xor_sync(0xFFFFFFFFu, part, 1);
        part *= __shfl_xor_sync(0xFFFFFFFFu, part, 2);
        part *= __shfl_xor_sync(0xFFFFFFFFu, part, 4);

        if (g == 7) {
            float s, b;
            if (part == 0.0f)      { s = 0.0f;            b = 0.0f; }
            else if (isinf(part))  { s = 1.0f / 20000.0f; b = 1.0f; }
            else                   { s = 1.0f / part;     b = 1.0f; }
            out1.x = s;
            out1.y = b;
        }

        if (live) {
            float4* out = (float4*)(g_rows + (size_t)(r0 + lr) * 64);
            out[g] = out1;                    // line 0: dims 0..13 + (s,b)
            if (g <= 5) out[8 + g] = out2;    // line 1: dims 14..24
        }
    }
}

// Full (rare) evaluation for one pair: shfl product over lane partials,
// plus line-1 dims when still positive. Returns group-uniform prod.
__device__ __forceinline__ float rare_full_prod(
    const float4* A, const float4* B, int g, float part)
{
    float prod = part;
    prod *= __shfl_xor_sync(0xFFFFFFFFu, prod, 1);
    prod *= __shfl_xor_sync(0xFFFFFFFFu, prod, 2);
    prod *= __shfl_xor_sync(0xFFFFFFFFu, prod, 4);

    if (__any_sync(0xFFFFFFFFu, prod > 0.0f)) {
        float extra = 1.0f;
        if (prod > 0.0f && g <= 5) {
            float4 a2 = __ldg(A + 8 + g);
            float4 b2 = __ldg(B + 8 + g);
            float u0 = fminf(a2.y, b2.y) - fmaxf(a2.x, b2.x);
            extra = fmaxf(u0, 0.0f);
            if (g <= 4) {
                float u1 = fminf(a2.w, b2.w) - fmaxf(a2.z, b2.z);
                extra *= fmaxf(u1, 0.0f);
            }
        }
        extra *= __shfl_xor_sync(0xFFFFFFFFu, extra, 1);
        extra *= __shfl_xor_sync(0xFFFFFFFFu, extra, 2);
        extra *= __shfl_xor_sync(0xFFFFFFFFu, extra, 4);
        prod *= extra;
    }
    return prod;
}

// One pair evaluation given its (register-resident) indices.
__device__ __forceinline__ void eval_pair(
    int ix, int iy, int g, int gsh, bool count, float& acc)
{
    const float4* A = (const float4*)(g_rows + (size_t)ix * 64);
    const float4* B = (const float4*)(g_rows + (size_t)iy * 64);

    float4 a1 = __ldg(A + g);
    float4 b1 = __ldg(B + g);

    float part, s = 0.0f, b = 0.0f;
    if (g < 7) {
        float w0 = fminf(a1.y, b1.y) - fmaxf(a1.x, b1.x);
        float w1 = fminf(a1.w, b1.w) - fmaxf(a1.z, b1.z);
        part = fmaxf(w0, 0.0f) * fmaxf(w1, 0.0f);
    } else {
        part = 1.0f;
        s = a1.x;
        b = a1.y;
    }

    unsigned ball = __ballot_sync(0xFFFFFFFFu, part > 0.0f);
    bool galive = (((ball >> gsh) & 0x7Fu) == 0x7Fu);

    if (__any_sync(0xFFFFFFFFu, galive)) {
        float prod = rare_full_prod(A, B, g, part);
        if (g == 7 && count) {
            float loss = b - prod * s;
            float rl = fmaxf(loss, 0.0f);
            acc += rl * rl;
        }
    } else {
        if (g == 7 && count) acc += b;   // inter==0 -> rl^2 = b in {0,1}
    }
}

// 8 lanes per pair, grid-stride. Indices are lane-distributed in chunks of 8
// and double-buffered, so the idx LDG leaves the per-iteration critical path;
// inside a chunk iteration k's index comes from 2 SHFLs (lane gsh+k).
__global__ __launch_bounds__(256)
void pairs_kernel(const int2* __restrict__ nf1, int n_pairs, int n_groups,
                  int n_full, int rem, float* __restrict__ out)
{
    int tid   = blockIdx.x * blockDim.x + threadIdx.x;
    int group = tid >> 3;
    int g     = tid & 7;
    int gsh   = threadIdx.x & 24;   // (group within warp) * 8

    float acc = 0.0f;

    int n_full8 = n_full & ~7;       // iterations handled in chunks of 8

    // preload chunk 0's indices (lane g -> iteration g)
    int2 myidx = make_int2(0, 0);
    if (n_full8 > 0)
        myidx = __ldg(nf1 + group + (size_t)g * n_groups);

    for (int it0 = 0; it0 < n_full8; it0 += 8) {
        int2 cur = myidx;
        // prefetch next chunk while this one computes
        if (it0 + 8 < n_full8)
            myidx = __ldg(nf1 + group + (size_t)(it0 + 8 + g) * n_groups);

#pragma unroll
        for (int k = 0; k < 8; k++) {
            int ix = __shfl_sync(0xFFFFFFFFu, cur.x, gsh + k);
            int iy = __shfl_sync(0xFFFFFFFFu, cur.y, gsh + k);
            eval_pair(ix, iy, g, gsh, true, acc);
        }
    }

    // leftover full iterations (< 8) + guarded remainder iteration
    int pair = group + n_full8 * n_groups;
    for (int it = n_full8; it < n_full; it++, pair += n_groups) {
        int2 p = __ldg(nf1 + pair);
        eval_pair(p.x, p.y, g, gsh, true, acc);
    }
    if (rem) {
        bool live = (pair < n_pairs);
        int pe = live ? pair : (n_pairs - 1);
        int2 p = __ldg(nf1 + pe);
        eval_pair(p.x, p.y, g, gsh, live, acc);
    }

    // warp reduce
#pragma unroll
    for (int off = 16; off > 0; off >>= 1)
        acc += __shfl_down_sync(0xFFFFFFFFu, acc, off);

    __shared__ float smred[8];
    int lane = threadIdx.x & 31;
    int wid  = threadIdx.x >> 5;
    if (lane == 0) smred[wid] = acc;
    __syncthreads();
    if (wid == 0) {
        float v = (lane < 8) ? smred[lane] : 0.0f;
#pragma unroll
        for (int off = 4; off > 0; off >>= 1)
            v += __shfl_down_sync(0xFFFFFFFFu, v, off);
        if (lane == 0) {
            atomicAdd(&g_acc, (double)v);
            __threadfence();
            unsigned int old = atomicAdd(&g_done, 1u);
            if (old == gridDim.x - 1) {
                double total = *((volatile double*)&g_acc);
                out[0] = (float)sqrt(total);
            }
        }
    }
}

extern "C" void kernel_launch(void* const* d_in, const int* in_sizes, int n_in,
                              void* d_out, int out_size)
{
    const float* class_embeds = (const float*)d_in[0];
    const int2*  nf1          = (const int2*)d_in[1];
    int n_classes = in_sizes[0] / 50;
    int n_pairs   = in_sizes[1] / 2;

    repack_kernel<<<(n_classes + RPB - 1) / RPB, 256>>>(class_embeds, n_classes);

    {
        const int grid = 2368;              // 2 short waves; backfill hides spread
        const int n_groups = grid * 256 / 8;
        int n_full = n_pairs / n_groups;
        int rem    = n_pairs % n_groups;
        pairs_kernel<<<grid, 256>>>(nf1, n_pairs, n_groups, n_full, rem, (float*)d_out);
    }
}